// round 11
// baseline (speedup 1.0000x reference)
#include <cuda_runtime.h>
#include <cuda_bf16.h>
#include <cstdint>

// ---------------------------------------------------------------------------
// Problem constants
// ---------------------------------------------------------------------------
#define DIM   4096
#define LAT   32768
#define NB    4096
#define TOPK  64

// GEMM tiling
#define BM      128
#define BN      128
#define BK      32                // bf16 elems per k-step (hi & lo planes each)
#define NKSTEP  (DIM / BK)        // 128
#define STAGES  4
#define A_STG   16384             // 128 rows * 128 B (64B hi + 64B lo)
#define B_STG   16384
#define STG     (A_STG + B_STG)   // 32768 B per stage

// top-k refinement band half-width (abs). GEMM abs error ~2e-6; 5e-4 = huge margin.
#define BAND_DELTA 5e-4f
#define MAXB 256

// ---------------------------------------------------------------------------
// Device scratch (__device__ globals; no allocation)
// ---------------------------------------------------------------------------
__device__ __nv_bfloat16 g_Ahi[(size_t)NB * DIM];     //  32 MB
__device__ __nv_bfloat16 g_Alo[(size_t)NB * DIM];     //  32 MB
__device__ __nv_bfloat16 g_Bhi[(size_t)LAT * DIM];    // 256 MB
__device__ __nv_bfloat16 g_Blo[(size_t)LAT * DIM];    // 256 MB
__device__ float g_zpre[(size_t)NB * LAT];            // 512 MB
__device__ float g_WdT[(size_t)LAT * DIM];            // 512 MB
__device__ int   g_selidx[NB * TOPK];
__device__ float g_selval[NB * TOPK];

// ---------------------------------------------------------------------------
// PTX helpers (non-arch-specific: sm_80 features only; plain compute_103-safe)
// ---------------------------------------------------------------------------
__device__ __forceinline__ uint32_t smem_u32(const void* p) {
    uint32_t a;
    asm("{ .reg .u64 t; cvta.to.shared.u64 t, %1; cvt.u32.u64 %0, t; }" : "=r"(a) : "l"(p));
    return a;
}

#define CP_ASYNC16(dst, src) \
    asm volatile("cp.async.cg.shared.global [%0], [%1], 16;" :: "r"(dst), "l"(src))
#define CP_COMMIT()  asm volatile("cp.async.commit_group;")
#define CP_WAIT(n)   asm volatile("cp.async.wait_group %0;" :: "n"(n))

#define LDSM4(R, addr) \
    asm volatile("ldmatrix.sync.aligned.m8n8.x4.shared.b16 {%0,%1,%2,%3}, [%4];" \
                 : "=r"((R)[0]), "=r"((R)[1]), "=r"((R)[2]), "=r"((R)[3]) : "r"(addr))

#define MMA_BF16(C, A, B0, B1) \
    asm volatile("mma.sync.aligned.m16n8k16.row.col.f32.bf16.bf16.f32 " \
                 "{%0,%1,%2,%3}, {%4,%5,%6,%7}, {%8,%9}, {%0,%1,%2,%3};" \
                 : "+f"((C)[0]), "+f"((C)[1]), "+f"((C)[2]), "+f"((C)[3]) \
                 : "r"((A)[0]), "r"((A)[1]), "r"((A)[2]), "r"((A)[3]), "r"(B0), "r"(B1))

// ---------------------------------------------------------------------------
// Split-bf16 conversion kernels (hi = rn(x), lo = rn(x - hi))
// ---------------------------------------------------------------------------
__device__ __forceinline__ void split2(float2 f, __nv_bfloat162& hi2, __nv_bfloat162& lo2) {
    __nv_bfloat16 h0 = __float2bfloat16(f.x);
    __nv_bfloat16 h1 = __float2bfloat16(f.y);
    hi2.x = h0; hi2.y = h1;
    lo2.x = __float2bfloat16(f.x - __bfloat162float(h0));
    lo2.y = __float2bfloat16(f.y - __bfloat162float(h1));
}

__global__ void __launch_bounds__(256) convert_h_kernel(const float* __restrict__ h) {
    size_t t = (size_t)blockIdx.x * 256 + threadIdx.x;
    float2 f = ((const float2*)h)[t];
    __nv_bfloat162 hi2, lo2;
    split2(f, hi2, lo2);
    ((__nv_bfloat162*)g_Ahi)[t] = hi2;
    ((__nv_bfloat162*)g_Alo)[t] = lo2;
}

__global__ void __launch_bounds__(256) convert_w_kernel(const float* __restrict__ W) {
    size_t t = (size_t)blockIdx.x * 256 + threadIdx.x;
    float2 f = ((const float2*)W)[t];
    __nv_bfloat162 hi2, lo2;
    split2(f, hi2, lo2);
    ((__nv_bfloat162*)g_Bhi)[t] = hi2;
    ((__nv_bfloat162*)g_Blo)[t] = lo2;
}

// ---------------------------------------------------------------------------
// Transpose W_dec [DIM, LAT] -> g_WdT [LAT, DIM]
// ---------------------------------------------------------------------------
__global__ void __launch_bounds__(256) transpose_kernel(const float* __restrict__ Wd) {
    __shared__ float tile[32][33];
    int lbase = blockIdx.x * 32, dbase = blockIdx.y * 32;
    int tx = threadIdx.x, ty = threadIdx.y;   // (32, 8)
#pragma unroll
    for (int j = 0; j < 4; ++j)
        tile[ty + j * 8][tx] = Wd[(size_t)(dbase + ty + j * 8) * LAT + lbase + tx];
    __syncthreads();
#pragma unroll
    for (int j = 0; j < 4; ++j)
        g_WdT[(size_t)(lbase + ty + j * 8) * DIM + dbase + tx] = tile[tx][ty + j * 8];
}

// ---------------------------------------------------------------------------
// Encode GEMM: z_pre = h @ W_enc^T, split-bf16 (hh + hl + lh), mma.sync
// CTA 128x128, 8 warps (4M x 2N), 4-stage cp.async, SW128-swizzled smem.
// ---------------------------------------------------------------------------
__device__ __forceinline__ void load_stage(uint32_t sbase, int slot, int kt,
                                           int m0, int n0, int tid) {
    uint32_t stg = sbase + slot * STG;
    int t = tid & 127;
    bool isB = tid >= 128;
    int base_row = isB ? n0 : m0;
    const __nv_bfloat16* hi = isB ? g_Bhi : g_Ahi;
    const __nv_bfloat16* lo = isB ? g_Blo : g_Alo;
    uint32_t dst0 = stg + (isB ? A_STG : 0);
#pragma unroll
    for (int j = 0; j < 8; ++j) {
        int gid = j * 128 + t;
        int row = gid >> 3;
        int g   = gid & 7;         // 16B granule: 0-3 hi, 4-7 lo
        const __nv_bfloat16* src =
            ((g < 4) ? hi : lo) + (size_t)(base_row + row) * DIM + kt + (g & 3) * 8;
        uint32_t col = (uint32_t)g * 16;
        uint32_t dst = dst0 + row * 128 + (col ^ (((uint32_t)row & 7) << 4));
        CP_ASYNC16(dst, src);
    }
}

__global__ void __launch_bounds__(256, 1) gemm_kernel() {
    extern __shared__ char smraw[];
    uint32_t sbase = (smem_u32(smraw) + 1023u) & ~1023u;

    int tid  = threadIdx.x;
    int lane = tid & 31;
    int wid  = tid >> 5;
    int m_tile = blockIdx.x & 31;       // M fastest -> B tiles shared by 32 CTAs
    int n_tile = blockIdx.x >> 5;
    int m0 = m_tile * BM, n0 = n_tile * BN;
    int mw = (wid & 3) * 32;
    int nw = (wid >> 2) * 64;

    float acc[2][8][4];
#pragma unroll
    for (int a = 0; a < 2; ++a)
#pragma unroll
        for (int b = 0; b < 8; ++b)
#pragma unroll
            for (int c = 0; c < 4; ++c) acc[a][b][c] = 0.0f;

#pragma unroll
    for (int s = 0; s < STAGES - 1; ++s) {
        load_stage(sbase, s, s * BK, m0, n0, tid);
        CP_COMMIT();
    }

    int rowA0 = mw + (lane & 15);
    int rowB0 = nw + (lane & 7) + ((lane & 16) ? 8 : 0);
    uint32_t khA = (lane & 16) ? 16u : 0u;
    uint32_t khB = (lane & 8)  ? 16u : 0u;

    for (int ks = 0; ks < NKSTEP; ++ks) {
        CP_WAIT(STAGES - 2);
        __syncthreads();

        int nxt = ks + STAGES - 1;
        if (nxt < NKSTEP) {
            load_stage(sbase, nxt & (STAGES - 1), nxt * BK, m0, n0, tid);
            CP_COMMIT();
        }

        uint32_t sA = sbase + (ks & (STAGES - 1)) * STG;
        uint32_t sB = sA + A_STG;

#pragma unroll
        for (int ksub = 0; ksub < 2; ++ksub) {
            uint32_t aH[2][4], aL[2][4], bH[8][2], bL[8][2];
            uint32_t kb = (uint32_t)ksub * 32;

#pragma unroll
            for (int mi = 0; mi < 2; ++mi) {
                int row = rowA0 + mi * 16;
                uint32_t xr = ((uint32_t)row & 7) << 4;
                uint32_t base = sA + row * 128;
                LDSM4(aH[mi], base + ((kb + khA) ^ xr));
                LDSM4(aL[mi], base + ((64u + kb + khA) ^ xr));
            }
#pragma unroll
            for (int ni = 0; ni < 4; ++ni) {
                int row = rowB0 + ni * 16;
                uint32_t xr = ((uint32_t)row & 7) << 4;
                uint32_t base = sB + row * 128;
                uint32_t rh[4], rl[4];
                LDSM4(rh, base + ((kb + khB) ^ xr));
                LDSM4(rl, base + ((64u + kb + khB) ^ xr));
                bH[2 * ni][0] = rh[0]; bH[2 * ni][1] = rh[1];
                bH[2 * ni + 1][0] = rh[2]; bH[2 * ni + 1][1] = rh[3];
                bL[2 * ni][0] = rl[0]; bL[2 * ni][1] = rl[1];
                bL[2 * ni + 1][0] = rl[2]; bL[2 * ni + 1][1] = rl[3];
            }
#pragma unroll
            for (int mi = 0; mi < 2; ++mi) {
#pragma unroll
                for (int t8 = 0; t8 < 8; ++t8) {
                    MMA_BF16(acc[mi][t8], aH[mi], bH[t8][0], bH[t8][1]);  // hi*hi
                    MMA_BF16(acc[mi][t8], aH[mi], bL[t8][0], bL[t8][1]);  // hi*lo
                    MMA_BF16(acc[mi][t8], aL[mi], bH[t8][0], bH[t8][1]);  // lo*hi
                }
            }
        }
    }

#pragma unroll
    for (int mi = 0; mi < 2; ++mi) {
#pragma unroll
        for (int t8 = 0; t8 < 8; ++t8) {
            int row = m0 + mw + mi * 16 + (lane >> 2);
            int col = n0 + nw + t8 * 8 + (lane & 3) * 2;
            float2 v0 = make_float2(acc[mi][t8][0], acc[mi][t8][1]);
            float2 v1 = make_float2(acc[mi][t8][2], acc[mi][t8][3]);
            *(float2*)&g_zpre[(size_t)row * LAT + col]       = v0;
            *(float2*)&g_zpre[(size_t)(row + 8) * LAT + col] = v1;
        }
    }
}

// ---------------------------------------------------------------------------
// Per-row top-64 radix select + exact fp32 boundary refinement
// ---------------------------------------------------------------------------
__device__ __forceinline__ unsigned sortkey(float f) {
    unsigned b = __float_as_uint(f);
    return (b & 0x80000000u) ? ~b : (b | 0x80000000u);
}
__device__ __forceinline__ float unsortkey(unsigned u) {
    unsigned b = (u & 0x80000000u) ? (u & 0x7FFFFFFFu) : ~u;
    return __uint_as_float(b);
}

__global__ void __launch_bounds__(512, 1) topk_kernel(const float* __restrict__ h,
                                                      const float* __restrict__ W_enc,
                                                      const float* __restrict__ b_enc,
                                                      float* __restrict__ z_out) {
    extern __shared__ unsigned skeys[];        // 32768 keys = 128 KB
    __shared__ unsigned hist[256];
    __shared__ unsigned sh_prefix, sh_rem;
    __shared__ unsigned sh_above, sh_nband;
    __shared__ int   bidx[MAXB];
    __shared__ float bval[MAXB];
    __shared__ unsigned char bsel[MAXB];
    __shared__ float red[16];
    __shared__ unsigned wcnt[16];
    __shared__ unsigned runbase;

    int row  = blockIdx.x;
    int tid  = threadIdx.x;
    int lane = tid & 31;
    int wid  = tid >> 5;
    const float* zp = g_zpre + (size_t)row * LAT;

    for (int i = tid; i < LAT; i += 512)
        skeys[i] = sortkey(zp[i] + b_enc[i]);
    if (tid == 0) { sh_prefix = 0; sh_rem = TOPK; sh_above = 0; sh_nband = 0; runbase = 0; }
    __syncthreads();

    // ---- radix select: find 64th-largest approximate key ----
    for (int level = 3; level >= 0; --level) {
        if (tid < 256) hist[tid] = 0;
        __syncthreads();
        unsigned prefix = sh_prefix;
        unsigned pmask  = (level == 3) ? 0u : (0xFFFFFFFFu << ((level + 1) * 8));
        int shift = level * 8;
        for (int i = tid; i < LAT; i += 512) {
            unsigned k = skeys[i];
            if ((k & pmask) == prefix) atomicAdd(&hist[(k >> shift) & 255], 1u);
        }
        __syncthreads();
        if (tid == 0) {
            unsigned rem = sh_rem;
            int b = 255;
            for (; b > 0; --b) {
                unsigned c = hist[b];
                if (c >= rem) break;
                rem -= c;
            }
            sh_prefix = prefix | ((unsigned)b << shift);
            sh_rem = rem;
        }
        __syncthreads();
    }

    unsigned T  = sh_prefix;
    float    Tv = unsortkey(T);
    unsigned keyHi = sortkey(Tv + BAND_DELTA);
    unsigned keyLo = sortkey(Tv - BAND_DELTA);

    // ---- band collection: elements within +-delta of threshold ----
    for (int i = tid; i < LAT; i += 512) {
        unsigned k = skeys[i];
        if (k > keyHi) atomicAdd(&sh_above, 1u);
        else if (k >= keyLo) {
            unsigned s = atomicAdd(&sh_nband, 1u);
            if (s < MAXB) bidx[s] = i;
        }
    }
    __syncthreads();

    int nb = (int)sh_nband; if (nb > MAXB) nb = MAXB;
    int kneed = TOPK - (int)sh_above;

    // ---- exact fp32 dot for each band member (block-cooperative) ----
    const float* hrow = h + (size_t)row * DIM;
    for (int j = 0; j < nb; ++j) {
        int l = bidx[j];
        const float* wrow = W_enc + (size_t)l * DIM;
        float p = 0.0f;
        int b0 = tid * 8;
#pragma unroll
        for (int q = 0; q < 8; ++q) p = fmaf(hrow[b0 + q], wrow[b0 + q], p);
#pragma unroll
        for (int off = 16; off > 0; off >>= 1) p += __shfl_down_sync(0xFFFFFFFFu, p, off);
        if (lane == 0) red[wid] = p;
        __syncthreads();
        if (tid == 0) {
            float r = 0.0f;
            for (int w = 0; w < 16; ++w) r += red[w];
            bval[j] = r + b_enc[l];
        }
        __syncthreads();
    }

    // ---- exact ranking inside the band (deterministic, jax tie order) ----
    if (tid < nb) {
        float v = bval[tid]; int id = bidx[tid];
        int r = 0;
        for (int m = 0; m < nb; ++m)
            if (bval[m] > v || (bval[m] == v && bidx[m] < id)) r++;
        bsel[tid] = (r < kneed) ? 1 : 0;
    }
    __syncthreads();

    // ---- final pass: dense z + deterministic compact (idx,val) lists ----
    float* zr = z_out + (size_t)row * LAT;
    for (int cbase = 0; cbase < LAT; cbase += 512) {
        int i = cbase + tid;
        unsigned k = skeys[i];
        bool take = false;
        float outv = 0.0f;
        if (k > keyHi) { take = true; outv = unsortkey(k); }
        else if (k >= keyLo) {
            for (int j = 0; j < nb; ++j)
                if (bidx[j] == i) { if (bsel[j]) { take = true; outv = bval[j]; } break; }
        }
        float relv = take ? fmaxf(outv, 0.0f) : 0.0f;
        zr[i] = relv;

        unsigned ball = __ballot_sync(0xFFFFFFFFu, take);
        if (lane == 0) wcnt[wid] = __popc(ball);
        __syncthreads();
        if (tid == 0) {
            unsigned s = runbase;
            for (int w = 0; w < 16; ++w) { unsigned c = wcnt[w]; wcnt[w] = s; s += c; }
            runbase = s;
        }
        __syncthreads();
        if (take) {
            unsigned slot = wcnt[wid] + __popc(ball & ((1u << lane) - 1u));
            if (slot < TOPK) {
                g_selidx[row * TOPK + slot] = i;
                g_selval[row * TOPK + slot] = relv;
            }
        }
        __syncthreads();
    }
}

// ---------------------------------------------------------------------------
// Sparse decode: h_hat[b] = b_dec + sum_k val_k * WdT[idx_k, :]
// ---------------------------------------------------------------------------
__global__ void __launch_bounds__(512) decode_kernel(const float* __restrict__ b_dec,
                                                     float* __restrict__ h_hat) {
    __shared__ int   sidx[TOPK];
    __shared__ float sval[TOPK];
    int b = blockIdx.x;
    if (threadIdx.x < TOPK) {
        sidx[threadIdx.x] = g_selidx[b * TOPK + threadIdx.x];
        sval[threadIdx.x] = g_selval[b * TOPK + threadIdx.x];
    }
    __syncthreads();

    int d0 = threadIdx.x * 8;
    float4 a0 = *(const float4*)(b_dec + d0);
    float4 a1 = *(const float4*)(b_dec + d0 + 4);
#pragma unroll 4
    for (int k = 0; k < TOPK; ++k) {
        const float4* w = (const float4*)(g_WdT + (size_t)sidx[k] * DIM + d0);
        float v = sval[k];
        float4 w0 = w[0], w1 = w[1];
        a0.x += v * w0.x; a0.y += v * w0.y; a0.z += v * w0.z; a0.w += v * w0.w;
        a1.x += v * w1.x; a1.y += v * w1.y; a1.z += v * w1.z; a1.w += v * w1.w;
    }
    *(float4*)(h_hat + (size_t)b * DIM + d0)     = a0;
    *(float4*)(h_hat + (size_t)b * DIM + d0 + 4) = a1;
}

// ---------------------------------------------------------------------------
// Launch: inputs h, W_enc, b_enc, W_dec, b_dec; out = [h_hat | z]
// ---------------------------------------------------------------------------
extern "C" void kernel_launch(void* const* d_in, const int* in_sizes, int n_in,
                              void* d_out, int out_size) {
    const float* h     = (const float*)d_in[0];
    const float* W_enc = (const float*)d_in[1];
    const float* b_enc = (const float*)d_in[2];
    const float* W_dec = (const float*)d_in[3];
    const float* b_dec = (const float*)d_in[4];
    float* out   = (float*)d_out;
    float* h_hat = out;
    float* z_out = out + (size_t)NB * DIM;

    const int GEMM_SMEM = STAGES * STG + 1024;    // 132 KB
    cudaFuncSetAttribute(gemm_kernel, cudaFuncAttributeMaxDynamicSharedMemorySize, GEMM_SMEM);
    cudaFuncSetAttribute(topk_kernel, cudaFuncAttributeMaxDynamicSharedMemorySize, LAT * 4);

    // 1) split-bf16 conversions
    convert_h_kernel<<<(unsigned)((size_t)NB * DIM / 2 / 256), 256>>>(h);
    convert_w_kernel<<<(unsigned)((size_t)LAT * DIM / 2 / 256), 256>>>(W_enc);

    // 2) transpose W_dec for coalesced sparse decode
    transpose_kernel<<<dim3(LAT / 32, DIM / 32), dim3(32, 8)>>>(W_dec);

    // 3) encode GEMM (split-bf16 x3, mma.sync)
    gemm_kernel<<<(NB / BM) * (LAT / BN), 256, GEMM_SMEM>>>();

    // 4) top-64 radix select + exact boundary refinement
    topk_kernel<<<NB, 512, LAT * 4>>>(h, W_enc, b_enc, z_out);

    // 5) sparse decode
    decode_kernel<<<NB, 512>>>(b_dec, h_hat);

    (void)in_sizes; (void)n_in; (void)out_size;
}